// round 15
// baseline (speedup 1.0000x reference)
#include <cuda_runtime.h>
#include <cuda_bf16.h>
#include <math.h>
#include <cstdint>

// Problem dims
#define BB   64
#define N1   1152
#define PP   8
#define N2   128
#define DD   16
#define NDD  2048

#define I_B  16                 // i's per CTA
#define NBI  (N1 / I_B)         // 72 i-chunks
#define BH   32                 // b's per CTA (b-half)
#define NT   256                // 8 warps; CTA covers one n-eighth (16 n)

typedef unsigned long long ull;

// Scratch (no allocations allowed -> device globals)
__device__ float  g_partial[NBI * BB * NDD];     // 37.75 MB per-(ichunk,b) partials
__device__ float  g_v0[BB * NDD];                // squashed v after iteration 0
__device__ float  g_Z8[8 * BB * N1];             // per-eighth softmax denominators
__device__ float4 g_W3[(size_t)N1 * 4096];       // 75.5 MB repacked W

// ---------------- f32x2 helpers (2x fp32 throughput on sm_103a) -------------
__device__ __forceinline__ ull d_fma2(ull a, ull b, ull c) {
    ull r; asm("fma.rn.f32x2 %0, %1, %2, %3;" : "=l"(r) : "l"(a), "l"(b), "l"(c)); return r;
}
__device__ __forceinline__ ull d_mul2(ull a, ull b) {
    ull r; asm("mul.rn.f32x2 %0, %1, %2;" : "=l"(r) : "l"(a), "l"(b)); return r;
}
__device__ __forceinline__ ull d_dup(float x) {
    ull r; unsigned u = __float_as_uint(x);
    asm("mov.b64 %0, {%1, %2};" : "=l"(r) : "r"(u), "r"(u)); return r;
}
__device__ __forceinline__ ull d_pack(float lo, float hi) {
    ull r; unsigned a = __float_as_uint(lo), b = __float_as_uint(hi);
    asm("mov.b64 %0, {%1, %2};" : "=l"(r) : "r"(a), "r"(b)); return r;
}
__device__ __forceinline__ float d_hadd(ull a) {
    unsigned lo, hi; asm("mov.b64 {%0, %1}, %2;" : "=r"(lo), "=r"(hi) : "l"(a));
    return __uint_as_float(lo) + __uint_as_float(hi);
}
__device__ __forceinline__ void d_unpack(ull a, float& lo, float& hi) {
    unsigned x, y; asm("mov.b64 {%0, %1}, %2;" : "=r"(x), "=r"(y) : "l"(a));
    lo = __uint_as_float(x); hi = __uint_as_float(y);
}

// ---------------------------------------------------------------------------
// Repack W via smem transpose (coalesced in AND out). One block per i.
// Output float4 index o = ((i*8 + e)*8 + w)*64 + p*8 + s, holding
//   { W[i, n, dq+0, p], ..., W[i, n, dq+3, p] },  n = 16e + 2w + (s>>2),
//   dq = (s&3)*4.  Main pass: lanes s=0..7 of a warp read 8 consecutive
//   float4s (4-way duplicated across g) -> exactly 1 L1 wavefront per LDG.
// ---------------------------------------------------------------------------
__global__ __launch_bounds__(256) void repack_W3(const float* __restrict__ W)
{
    extern __shared__ float buf[];                // 16384 floats = 64 KB
    const size_t i  = blockIdx.x;
    const int   tid = threadIdx.x;
    for (int t = tid; t < 16384; t += 256) buf[t] = W[i * 16384 + t];
    __syncthreads();
    for (int o = tid; o < 4096; o += 256) {
        const int s = o & 7, p = (o >> 3) & 7, w = (o >> 6) & 7, e = o >> 9;
        const int n  = e * 16 + w * 2 + (s >> 2);
        const int dq = (s & 3) * 4;
        float4 v;
        v.x = buf[n * 128 + (dq + 0) * 8 + p];
        v.y = buf[n * 128 + (dq + 1) * 8 + p];
        v.z = buf[n * 128 + (dq + 2) * 8 + p];
        v.w = buf[n * 128 + (dq + 3) * 8 + p];
        g_W3[i * 4096 + o] = v;
    }
}

// ---------------------------------------------------------------------------
// smem layout (bytes)
#define SMO_X2   0        // 4096 ull = 32768 (x dup'd as f32x2: [32 b][16 ii][8 p])
#define SMO_V0   32768    // 8192 f   = 32768 (MODE>=1: [32 b][16 nl][16 d] slice)
#define SMO_SZ   65536    // MODE 1: 16*8*32 f = 16384 (per-(ii,warp,b) e-sums)
#define SMO_ZI   65536    // MODE 2: 16*32 f   = 2048  (precomputed 1/Z)
#define SMEM_M0  32768
#define SMEM_M1  81920
#define SMEM_M2  67584

// Streaming kernel, 3 modes, zero in-loop synchronization.
//   MODE 0: sacc += pred                        (iteration 0, uniform c)
//   MODE 1: Z8[e][b][i] = sum_{16 n} exp(<pred, v0>)
//   MODE 2: sacc += (e * 1/Z[b,i]) * pred       (Z precomputed)
// CTA = (b-half bh: 32 b, n-eighth e: 16 n, i-chunk: 16 i).
// Lane: slot s=l&7 -> (nl = 2w + (s>>2), dq = (s&3)*4); group g=l>>3 -> 8 b.
// ---------------------------------------------------------------------------
template<int MODE>
__global__ __launch_bounds__(NT, 2)
void caps_pass(const float* __restrict__ x, const float* __restrict__ v0in)
{
    extern __shared__ char smraw[];
    ull*   x2   = (ull*)(smraw + SMO_X2);
    float* v0s  = (float*)(smraw + SMO_V0);
    float* sZ   = (float*)(smraw + SMO_SZ);     // MODE 1
    float* zinv = (float*)(smraw + SMO_ZI);     // MODE 2

    const int tid = threadIdx.x;
    const int w   = tid >> 5;
    const int l   = tid & 31;
    const int s   = l & 7;
    const int g   = l >> 3;
    const int e   = blockIdx.x & 7;
    const int bh  = blockIdx.x >> 3;
    const int ic  = blockIdx.y;
    const int i0  = ic * I_B;
    const int b0  = bh * BH;
    const int nl  = w * 2 + (s >> 2);           // n within eighth [0,16)
    const int dq  = (s & 3) * 4;
    const int bl0 = g * 8;                      // lane's local-b base

    // stage x duplicated as f32x2: x2[(bl*16 + ii)*8 + p]
    for (int t = tid; t < BH * I_B * PP; t += NT) {
        const int bl = t >> 7, rem = t & 127;
        x2[t] = d_dup(x[(size_t)(b0 + bl) * (N1 * PP) + (size_t)i0 * PP + rem]);
    }
    if (MODE >= 1) {
        for (int t = tid; t < BH * 256; t += NT) {        // v0 slice for this eighth
            const int bl = t >> 8, rem = t & 255;         // rem = nl*16 + d
            v0s[t] = v0in[(size_t)(b0 + bl) * NDD + e * 256 + rem];
        }
    }
    if (MODE == 2) {
        for (int t = tid; t < I_B * BH; t += NT) {        // 1/Z for (ii, bl)
            const int ii = t >> 5, bl = t & 31;
            const size_t zi = (size_t)(b0 + bl) * N1 + (i0 + ii);
            float Z = 0.0f;
#pragma unroll
            for (int q = 0; q < 8; ++q) Z += g_Z8[(size_t)q * (BB * N1) + zi];
            zinv[t] = __fdividef(1.0f, Z);
        }
    }
    __syncthreads();

    ull sacc[8][2];
    if (MODE != 1) {
#pragma unroll
        for (int k = 0; k < 8; ++k) { sacc[k][0] = 0ull; sacc[k][1] = 0ull; }
    }

#pragma unroll 1
    for (int ii = 0; ii < I_B; ++ii) {
        // W frag: 8 float4 for this lane's slot; 1 wavefront per LDG
        const ulonglong2* Wp = (const ulonglong2*)(g_W3
            + (((size_t)(i0 + ii) * 8 + e) * 8 + w) * 64);
        ulonglong2 wv[8];
#pragma unroll
        for (int p = 0; p < 8; ++p) wv[p] = Wp[p * 8 + s];

#pragma unroll
        for (int k = 0; k < 8; ++k) {
            const int bl = bl0 + k;
            const ulonglong2* xq = (const ulonglong2*)(x2 + (bl * I_B + ii) * 8);
            const ulonglong2 x01 = xq[0], x23 = xq[1], x45 = xq[2], x67 = xq[3];

            ull a, b;
            if (MODE == 0) { a = sacc[k][0]; b = sacc[k][1];
                a = d_fma2(x01.x, wv[0].x, a); b = d_fma2(x01.x, wv[0].y, b);
            } else {
                a = d_mul2(x01.x, wv[0].x);    b = d_mul2(x01.x, wv[0].y);
            }
            a = d_fma2(x01.y, wv[1].x, a); b = d_fma2(x01.y, wv[1].y, b);
            a = d_fma2(x23.x, wv[2].x, a); b = d_fma2(x23.x, wv[2].y, b);
            a = d_fma2(x23.y, wv[3].x, a); b = d_fma2(x23.y, wv[3].y, b);
            a = d_fma2(x45.x, wv[4].x, a); b = d_fma2(x45.x, wv[4].y, b);
            a = d_fma2(x45.y, wv[5].x, a); b = d_fma2(x45.y, wv[5].y, b);
            a = d_fma2(x67.x, wv[6].x, a); b = d_fma2(x67.x, wv[6].y, b);
            a = d_fma2(x67.y, wv[7].x, a); b = d_fma2(x67.y, wv[7].y, b);

            if (MODE == 0) {
                sacc[k][0] = a; sacc[k][1] = b;
            } else {
                // r = <pred, v0> for (b0+bl, n = 16e+nl); quad holds 16 d
                const float4 vv = *(const float4*)&v0s[bl * 256 + nl * DD + dq];
                const ull t2 = d_fma2(a, d_pack(vv.x, vv.y),
                                      d_mul2(b, d_pack(vv.z, vv.w)));
                float r = d_hadd(t2);
                r += __shfl_xor_sync(0xFFFFFFFFu, r, 1);
                r += __shfl_xor_sync(0xFFFFFFFFu, r, 2);
                const float ev = __expf(r);               // |r| bounded; no max-sub

                if (MODE == 1) {
                    // pair-sum the warp's two n, one writer per (g, warp)
                    const float ep = ev + __shfl_xor_sync(0xFFFFFFFFu, ev, 4);
                    if (s == 0) sZ[(ii * 8 + w) * BH + bl] = ep;
                } else {                                  // MODE 2
                    const ull cd = d_dup(ev * zinv[ii * BH + bl]);
                    sacc[k][0] = d_fma2(cd, a, sacc[k][0]);
                    sacc[k][1] = d_fma2(cd, b, sacc[k][1]);
                }
            }
        }
    }

    if (MODE == 1) {
        __syncthreads();                                  // only barrier in kernel
        for (int t = tid; t < I_B * BH; t += NT) {
            const int ii = t >> 5, bl = t & 31;
            float z = 0.0f;
#pragma unroll
            for (int q = 0; q < 8; ++q) z += sZ[(ii * 8 + q) * BH + bl];
            g_Z8[(size_t)e * (BB * N1) + (size_t)(b0 + bl) * N1 + (i0 + ii)] = z;
        }
    } else {
        // write per-(ichunk,b) partials for this eighth's n
#pragma unroll
        for (int k = 0; k < 8; ++k) {
            float4 o;
            d_unpack(sacc[k][0], o.x, o.y);
            d_unpack(sacc[k][1], o.z, o.w);
            float* gp = g_partial + ((size_t)ic * BB + (b0 + bl0 + k)) * NDD
                      + (e * 16 + nl) * DD + dq;
            *(float4*)gp = o;
        }
    }
}

// ---------------------------------------------------------------------------
// Reduce the NBI partials, scale, squash, write out.
// 4 lanes per (b,n) row; quad shuffles for the norm.
// ---------------------------------------------------------------------------
__global__ __launch_bounds__(256) void reduce_squash_kernel(float* __restrict__ out, float scale)
{
    const int t = blockIdx.x * 256 + threadIdx.x;
    const int r = t >> 2;
    const int quad = t & 3;

    float4 s = make_float4(0.f, 0.f, 0.f, 0.f);
#pragma unroll 4
    for (int blk = 0; blk < NBI; ++blk) {
        const float4 a = *(const float4*)(g_partial
            + ((size_t)blk * (BB * N2) + r) * DD + quad * 4);
        s.x += a.x; s.y += a.y; s.z += a.z; s.w += a.w;
    }
    s.x *= scale; s.y *= scale; s.z *= scale; s.w *= scale;

    float sq = s.x * s.x + s.y * s.y + s.z * s.z + s.w * s.w;
    sq += __shfl_xor_sync(0xFFFFFFFFu, sq, 1);
    sq += __shfl_xor_sync(0xFFFFFFFFu, sq, 2);

    const float norm = sqrtf(sq + 1.1920929e-7f);
    const float f = sq / ((1.0f + sq) * norm);
    *(float4*)(out + (size_t)r * DD + quad * 4) =
        make_float4(f * s.x, f * s.y, f * s.z, f * s.w);
}

// ---------------------------------------------------------------------------
extern "C" void kernel_launch(void* const* d_in, const int* in_sizes, int n_in,
                              void* d_out, int out_size)
{
    const float* x = (const float*)d_in[0];
    const float* W = (const float*)d_in[1];
    if (n_in >= 2 && in_sizes[0] > in_sizes[1]) {   // safety: x is the smaller tensor
        const float* t = x; x = W; W = t;
    }
    float* out = (float*)d_out;

    float* d_v0;
    cudaGetSymbolAddress((void**)&d_v0, g_v0);

    cudaFuncSetAttribute(repack_W3,
                         cudaFuncAttributeMaxDynamicSharedMemorySize, 65536);
    cudaFuncSetAttribute(caps_pass<1>,
                         cudaFuncAttributeMaxDynamicSharedMemorySize, SMEM_M1);
    cudaFuncSetAttribute(caps_pass<2>,
                         cudaFuncAttributeMaxDynamicSharedMemorySize, SMEM_M2);

    // repack W (smem transpose, coalesced both ways)
    repack_W3<<<N1, 256, 65536>>>(W);

    dim3 grid(16, NBI);       // (b-half*8 + n-eighth, i-chunk) = 1152 CTAs

    // iteration 0: uniform coupling -> s0 = (1/128) * sum_i pred
    caps_pass<0><<<grid, NT, SMEM_M0>>>(x, nullptr);
    reduce_squash_kernel<<<128, 256>>>(d_v0, 1.0f / 128.0f);

    // iteration 1: Z pass, then barrier-free weighted pass
    caps_pass<1><<<grid, NT, SMEM_M1>>>(x, d_v0);
    caps_pass<2><<<grid, NT, SMEM_M2>>>(x, d_v0);
    reduce_squash_kernel<<<128, 256>>>(out, 1.0f);
}

// round 16
// speedup vs baseline: 1.6282x; 1.6282x over previous
#include <cuda_runtime.h>
#include <cuda_bf16.h>
#include <math.h>
#include <cstdint>

// Problem dims
#define BB   64
#define N1   1152
#define PP   8
#define N2   128
#define DD   16
#define NDD  2048

#define I_B  64                 // i's per CTA (both passes)
#define NBI  (N1 / I_B)         // 18
#define NT   256

typedef unsigned long long ull;

// Scratch (no allocations allowed -> device globals)
__device__ float  g_partial[NBI * BB * NDD];     // 9.44 MB per-(iblock,b) partials
__device__ float  g_v0[BB * NDD];                // squashed v after iteration 0
__device__ float4 g_W3[(size_t)N1 * 4096];       // 75.5 MB repacked W

// ---------------- f32x2 helpers (2x fp32 throughput on sm_103a) -------------
__device__ __forceinline__ ull d_fma2(ull a, ull b, ull c) {
    ull r; asm("fma.rn.f32x2 %0, %1, %2, %3;" : "=l"(r) : "l"(a), "l"(b), "l"(c)); return r;
}
__device__ __forceinline__ ull d_mul2(ull a, ull b) {
    ull r; asm("mul.rn.f32x2 %0, %1, %2;" : "=l"(r) : "l"(a), "l"(b)); return r;
}
__device__ __forceinline__ ull d_add2(ull a, ull b) {
    ull r; asm("add.rn.f32x2 %0, %1, %2;" : "=l"(r) : "l"(a), "l"(b)); return r;
}
__device__ __forceinline__ ull d_dup(float x) {
    ull r; unsigned u = __float_as_uint(x);
    asm("mov.b64 %0, {%1, %2};" : "=l"(r) : "r"(u), "r"(u)); return r;
}
__device__ __forceinline__ ull d_pack(float lo, float hi) {
    ull r; unsigned a = __float_as_uint(lo), b = __float_as_uint(hi);
    asm("mov.b64 %0, {%1, %2};" : "=l"(r) : "r"(a), "r"(b)); return r;
}
__device__ __forceinline__ float d_hadd(ull a) {
    unsigned lo, hi; asm("mov.b64 {%0, %1}, %2;" : "=r"(lo), "=r"(hi) : "l"(a));
    return __uint_as_float(lo) + __uint_as_float(hi);
}
__device__ __forceinline__ void d_unpack(ull a, float& lo, float& hi) {
    unsigned x, y; asm("mov.b64 {%0, %1}, %2;" : "=r"(x), "=r"(y) : "l"(a));
    lo = __uint_as_float(x); hi = __uint_as_float(y);
}

// ---------------------------------------------------------------------------
// Repack W via smem transpose (coalesced in AND out). One block per i.
// Output float4 o = ((i*8 + e)*8 + w)*64 + p*8 + s holds
//   { W[i, n, dq+0, p], ..., W[i, n, dq+3, p] },  n = 16e + 2w + (s>>2),
//   dq = (s&3)*4.  Any (n, dq, p-range) fragment is addressable:
//   e = n>>4, w = (n>>1)&7, s = (n&1)*4 + dq/4.
// ---------------------------------------------------------------------------
__global__ __launch_bounds__(256) void repack_W3(const float* __restrict__ W)
{
    extern __shared__ float buf[];                // 16384 floats = 64 KB
    const size_t i  = blockIdx.x;
    const int   tid = threadIdx.x;
    for (int t = tid; t < 16384; t += 256) buf[t] = W[i * 16384 + t];
    __syncthreads();
    for (int o = tid; o < 4096; o += 256) {
        const int s = o & 7, p = (o >> 3) & 7, w = (o >> 6) & 7, e = o >> 9;
        const int n  = e * 16 + w * 2 + (s >> 2);
        const int dq = (s & 3) * 4;
        float4 v;
        v.x = buf[n * 128 + (dq + 0) * 8 + p];
        v.y = buf[n * 128 + (dq + 1) * 8 + p];
        v.z = buf[n * 128 + (dq + 2) * 8 + p];
        v.w = buf[n * 128 + (dq + 3) * 8 + p];
        g_W3[i * 4096 + o] = v;
    }
}

// ---------------------------------------------------------------------------
// Pass 0 (uniform coupling): sacc += pred, streamed, zero in-loop sync.
// CTA = (n-eighth e: 16 n, b-half bh: 32 b, i-block: 64 i).
// Lane: slot s=l&7 -> (nl = 2w + (s>>2), dq = (s&3)*4); group g=l>>3.
// Lane's 8 b: bl = 4k+g  (4 groups 4B apart -> conflict-free 1-wf LDS).
// W: lanes s=0..7 read 8 consecutive float4 (4-way dup) -> 1 wf per LDG.
// x staged pad-33: xs[(ii*8+p)*33 + bl]  (STS and LDS both conflict-free).
// ---------------------------------------------------------------------------
#define SMEM_P0 (512 * 33 * 4)   // 67584 B
__global__ __launch_bounds__(NT, 2)
void caps_pass0(const float* __restrict__ x)
{
    extern __shared__ float xs[];
    const int tid = threadIdx.x;
    const int w   = tid >> 5;
    const int l   = tid & 31;
    const int s   = l & 7;
    const int g   = l >> 3;
    const int e   = blockIdx.x & 7;
    const int bh  = blockIdx.x >> 3;
    const int ic  = blockIdx.y;
    const int i0  = ic * I_B;
    const int b0  = bh * 32;
    const int nl  = w * 2 + (s >> 2);       // n within eighth
    const int dq  = (s & 3) * 4;

    // stage x: gmem read coalesced over rem=(ii*8+p); pad-33 kills STS conflicts
    for (int t = tid; t < 32 * I_B * PP; t += NT) {
        const int bl = t >> 9, rem = t & 511;
        xs[rem * 33 + bl] = x[(size_t)(b0 + bl) * (N1 * PP) + (size_t)i0 * PP + rem];
    }
    __syncthreads();

    ull sacc[8][2];
#pragma unroll
    for (int k = 0; k < 8; ++k) { sacc[k][0] = 0ull; sacc[k][1] = 0ull; }

#pragma unroll 1
    for (int ii = 0; ii < I_B; ++ii) {
        const ulonglong2* Wp = (const ulonglong2*)(g_W3
            + (((size_t)(i0 + ii) * 8 + e) * 8 + w) * 64);
        ulonglong2 wv[8];
#pragma unroll
        for (int p = 0; p < 8; ++p) wv[p] = Wp[p * 8 + s];   // 1 wf per LDG

        const float* xr = xs + ii * (8 * 33);
#pragma unroll
        for (int k = 0; k < 8; ++k) {
            const int bl = k * 4 + g;
            ull a = sacc[k][0], b = sacc[k][1];
#pragma unroll
            for (int p = 0; p < 8; ++p) {
                const ull xp = d_dup(xr[p * 33 + bl]);       // 1-wf LDS.32 + dup
                a = d_fma2(xp, wv[p].x, a);
                b = d_fma2(xp, wv[p].y, b);
            }
            sacc[k][0] = a; sacc[k][1] = b;
        }
    }

#pragma unroll
    for (int k = 0; k < 8; ++k) {
        float4 o;
        d_unpack(sacc[k][0], o.x, o.y);
        d_unpack(sacc[k][1], o.z, o.w);
        float* gp = g_partial + ((size_t)ic * BB + (b0 + k * 4 + g)) * NDD
                  + (e * 16 + nl) * DD + dq;
        *(float4*)gp = o;
    }
}

// ---------------------------------------------------------------------------
// Routing pass (round-7 structure, known good): block softmax, one barrier
// per ii, 2 CTA/SM. Warp w owns n-groups {8w..8w+8} and {64+8w..}; lane:
// n = 8w + (l>>2) (+64g2), dq = (l&3)*4. Only change: W read from g_W3.
// ---------------------------------------------------------------------------
#define BG   4
#define NBB  (BB / BG)          // 16
#define SMEM_RT ((4096 + 8192) * 4 + 2 * 8 * 4 * 8)   // 49.4 KB

__global__ __launch_bounds__(NT, 2)
void caps_route(const float* __restrict__ x, const float* __restrict__ v0in)
{
    extern __shared__ float sm[];
    ull*    x2  = (ull*)sm;                       // 2048 ull = 16 KB (dup'd x)
    float*  v0s = sm + 4096;                      // 8192 f = 32 KB
    float2* red = (float2*)(sm + 4096 + 8192);    // 2*8*4 float2

    const int tid = threadIdx.x;
    const int w   = tid >> 5;
    const int l   = tid & 31;
    const int nb  = w * 8 + (l >> 2);             // n for g2=0 (g2=1: +64)
    const int dq  = (l & 3) * 4;
    const int ib0 = blockIdx.x * I_B;
    const int b0  = blockIdx.y * BG;

    // per-group W3 fragment base (float4 units within one i's 4096 block)
    int wbase[2];
#pragma unroll
    for (int g2 = 0; g2 < 2; ++g2) {
        const int n_g = nb + 64 * g2;
        const int e2  = n_g >> 4;
        const int ww  = (n_g >> 1) & 7;
        const int s2  = (n_g & 1) * 4 + (l & 3);
        wbase[g2] = (e2 * 8 + ww) * 64 + s2;
    }

    // stage x duplicated as f32x2: x2[bb*512 + ii*8 + p]
    for (int t = tid; t < BG * I_B * PP; t += NT) {
        const int bb = t >> 9, rem = t & 511;
        x2[t] = d_dup(x[(size_t)(b0 + bb) * (N1 * PP) + (size_t)ib0 * PP + rem]);
    }
    for (int t = tid; t < BG * NDD; t += NT) {
        const int bb = t >> 11, rem = t & 2047;
        v0s[t] = v0in[(size_t)(b0 + bb) * NDD + rem];
    }
    __syncthreads();

    ull sacc[2][BG][2];
#pragma unroll
    for (int g2 = 0; g2 < 2; ++g2)
#pragma unroll
        for (int bb = 0; bb < BG; ++bb) { sacc[g2][bb][0] = 0ull; sacc[g2][bb][1] = 0ull; }

#pragma unroll 1
    for (int ii = 0; ii < I_B; ++ii) {
        const ulonglong2* Wi = (const ulonglong2*)(g_W3 + (((size_t)(ib0 + ii)) << 12));

        ull pr[2][BG][2];
        float S[2][BG];
#pragma unroll
        for (int g2 = 0; g2 < 2; ++g2) {
            ulonglong2 wv[8];
#pragma unroll
            for (int p = 0; p < 8; ++p) wv[p] = Wi[wbase[g2] + p * 8];
#pragma unroll
            for (int bb = 0; bb < BG; ++bb) {
                const ulonglong2* xq = (const ulonglong2*)(x2 + bb * 512 + ii * 8);
                const ulonglong2 x01 = xq[0], x23 = xq[1], x45 = xq[2], x67 = xq[3];
                ull a = d_mul2(x01.x, wv[0].x);
                ull b = d_mul2(x01.x, wv[0].y);
                a = d_fma2(x01.y, wv[1].x, a); b = d_fma2(x01.y, wv[1].y, b);
                a = d_fma2(x23.x, wv[2].x, a); b = d_fma2(x23.x, wv[2].y, b);
                a = d_fma2(x23.y, wv[3].x, a); b = d_fma2(x23.y, wv[3].y, b);
                a = d_fma2(x45.x, wv[4].x, a); b = d_fma2(x45.x, wv[4].y, b);
                a = d_fma2(x45.y, wv[5].x, a); b = d_fma2(x45.y, wv[5].y, b);
                a = d_fma2(x67.x, wv[6].x, a); b = d_fma2(x67.x, wv[6].y, b);
                a = d_fma2(x67.y, wv[7].x, a); b = d_fma2(x67.y, wv[7].y, b);
                pr[g2][bb][0] = a; pr[g2][bb][1] = b;

                // agreement + exp + warp sum over this group's 8 n
                const float4 vv = *(const float4*)&v0s[bb * NDD + (nb + 64 * g2) * DD + dq];
                const ull t = d_fma2(a, d_pack(vv.x, vv.y), d_mul2(b, d_pack(vv.z, vv.w)));
                float r = d_hadd(t);
                r += __shfl_xor_sync(0xFFFFFFFFu, r, 1);
                r += __shfl_xor_sync(0xFFFFFFFFu, r, 2);      // full 16-d dot
                const float e = __expf(r);                    // |r| small; no max-sub
                float Sg = e;
                Sg += __shfl_xor_sync(0xFFFFFFFFu, Sg, 4);
                Sg += __shfl_xor_sync(0xFFFFFFFFu, Sg, 8);
                Sg += __shfl_xor_sync(0xFFFFFFFFu, Sg, 16);   // sum of 8 n
                S[g2][bb] = Sg;
                const ull ed = d_dup(e);
                pr[g2][bb][0] = d_mul2(pr[g2][bb][0], ed);    // fold e into pred
                pr[g2][bb][1] = d_mul2(pr[g2][bb][1], ed);
            }
        }
        const int buf = ii & 1;
        if (l == 0) {
#pragma unroll
            for (int bb = 0; bb < BG; ++bb)
                red[(buf * 8 + w) * 4 + bb] = make_float2(S[0][bb], S[1][bb]);
        }
        __syncthreads();                                      // one barrier per ii

        // Z[bb] = sum over 8 warps x 2 groups (broadcast LDS + f32x2 adds)
        ull z[BG] = {0ull, 0ull, 0ull, 0ull};
#pragma unroll
        for (int k = 0; k < 8; ++k) {
            const ulonglong2* rp = (const ulonglong2*)&red[(buf * 8 + k) * 4];
            const ulonglong2 a = rp[0], b = rp[1];
            z[0] = d_add2(z[0], a.x); z[1] = d_add2(z[1], a.y);
            z[2] = d_add2(z[2], b.x); z[3] = d_add2(z[3], b.y);
        }
#pragma unroll
        for (int bb = 0; bb < BG; ++bb) {
            const float Z = d_hadd(z[bb]);                    // sum over all 128 n
            const ull cd  = d_dup(__fdividef(1.0f, Z));
            sacc[0][bb][0] = d_fma2(cd, pr[0][bb][0], sacc[0][bb][0]);
            sacc[0][bb][1] = d_fma2(cd, pr[0][bb][1], sacc[0][bb][1]);
            sacc[1][bb][0] = d_fma2(cd, pr[1][bb][0], sacc[1][bb][0]);
            sacc[1][bb][1] = d_fma2(cd, pr[1][bb][1], sacc[1][bb][1]);
        }
    }

    // write per-(iblock,b) partials
#pragma unroll
    for (int g2 = 0; g2 < 2; ++g2)
#pragma unroll
        for (int bb = 0; bb < BG; ++bb) {
            float4 o;
            d_unpack(sacc[g2][bb][0], o.x, o.y);
            d_unpack(sacc[g2][bb][1], o.z, o.w);
            float* gp = g_partial + ((size_t)blockIdx.x * BB + (b0 + bb)) * NDD
                      + (nb + 64 * g2) * DD + dq;
            *(float4*)gp = o;
        }
}

// ---------------------------------------------------------------------------
// Reduce the NBI partials, scale, squash, write out.
// 4 lanes per (b,n) row; quad shuffles for the norm.
// ---------------------------------------------------------------------------
__global__ __launch_bounds__(256) void reduce_squash_kernel(float* __restrict__ out, float scale)
{
    const int t = blockIdx.x * 256 + threadIdx.x;
    const int r = t >> 2;
    const int quad = t & 3;

    float4 s = make_float4(0.f, 0.f, 0.f, 0.f);
#pragma unroll 3
    for (int blk = 0; blk < NBI; ++blk) {
        const float4 a = *(const float4*)(g_partial
            + ((size_t)blk * (BB * N2) + r) * DD + quad * 4);
        s.x += a.x; s.y += a.y; s.z += a.z; s.w += a.w;
    }
    s.x *= scale; s.y *= scale; s.z *= scale; s.w *= scale;

    float sq = s.x * s.x + s.y * s.y + s.z * s.z + s.w * s.w;
    sq += __shfl_xor_sync(0xFFFFFFFFu, sq, 1);
    sq += __shfl_xor_sync(0xFFFFFFFFu, sq, 2);

    const float norm = sqrtf(sq + 1.1920929e-7f);
    const float f = sq / ((1.0f + sq) * norm);
    *(float4*)(out + (size_t)r * DD + quad * 4) =
        make_float4(f * s.x, f * s.y, f * s.z, f * s.w);
}

// ---------------------------------------------------------------------------
extern "C" void kernel_launch(void* const* d_in, const int* in_sizes, int n_in,
                              void* d_out, int out_size)
{
    const float* x = (const float*)d_in[0];
    const float* W = (const float*)d_in[1];
    if (n_in >= 2 && in_sizes[0] > in_sizes[1]) {   // safety: x is the smaller tensor
        const float* t = x; x = W; W = t;
    }
    float* out = (float*)d_out;

    float* d_v0;
    cudaGetSymbolAddress((void**)&d_v0, g_v0);

    cudaFuncSetAttribute(repack_W3,
                         cudaFuncAttributeMaxDynamicSharedMemorySize, 65536);
    cudaFuncSetAttribute(caps_pass0,
                         cudaFuncAttributeMaxDynamicSharedMemorySize, SMEM_P0);
    cudaFuncSetAttribute(caps_route,
                         cudaFuncAttributeMaxDynamicSharedMemorySize, SMEM_RT);

    // repack W (smem transpose, coalesced both ways) -- serves both passes
    repack_W3<<<N1, 256, 65536>>>(W);

    // iteration 0: uniform coupling -> s0 = (1/128) * sum_i pred
    dim3 grid0(16, NBI);                  // (bh*8 + e, i-block) = 288 CTAs
    caps_pass0<<<grid0, NT, SMEM_P0>>>(x);
    reduce_squash_kernel<<<128, 256>>>(d_v0, 1.0f / 128.0f);

    // iteration 1: softmax(agreement) routing, final squash -> output
    dim3 grid1(NBI, NBB);                 // (i-block, b-block) = 288 CTAs
    caps_route<<<grid1, NT, SMEM_RT>>>(x, d_v0);
    reduce_squash_kernel<<<128, 256>>>(out, 1.0f);
}

// round 17
// speedup vs baseline: 1.7060x; 1.0478x over previous
#include <cuda_runtime.h>
#include <cuda_bf16.h>
#include <math.h>
#include <cstdint>

// Problem dims
#define BB   64
#define N1   1152
#define PP   8
#define N2   128
#define DD   16
#define NDD  2048

#define I_B  64                 // i's per CTA (both passes)
#define NBI  (N1 / I_B)         // 18
#define NT   256

typedef unsigned long long ull;

// Scratch (no allocations allowed -> device globals)
__device__ float  g_partial[NBI * BB * NDD];     // 9.44 MB per-(iblock,b) partials
__device__ float  g_v0[BB * NDD];                // squashed v after iteration 0
__device__ float4 g_W2[(size_t)N1 * 4096];       // 75.5 MB repacked W (d-pair layout)

// ---------------- f32x2 helpers (2x fp32 throughput on sm_103a) -------------
__device__ __forceinline__ ull d_fma2(ull a, ull b, ull c) {
    ull r; asm("fma.rn.f32x2 %0, %1, %2, %3;" : "=l"(r) : "l"(a), "l"(b), "l"(c)); return r;
}
__device__ __forceinline__ ull d_mul2(ull a, ull b) {
    ull r; asm("mul.rn.f32x2 %0, %1, %2;" : "=l"(r) : "l"(a), "l"(b)); return r;
}
__device__ __forceinline__ ull d_add2(ull a, ull b) {
    ull r; asm("add.rn.f32x2 %0, %1, %2;" : "=l"(r) : "l"(a), "l"(b)); return r;
}
__device__ __forceinline__ ull d_dup(float x) {
    ull r; unsigned u = __float_as_uint(x);
    asm("mov.b64 %0, {%1, %2};" : "=l"(r) : "r"(u), "r"(u)); return r;
}
__device__ __forceinline__ ull d_pack(float lo, float hi) {
    ull r; unsigned a = __float_as_uint(lo), b = __float_as_uint(hi);
    asm("mov.b64 %0, {%1, %2};" : "=l"(r) : "r"(a), "r"(b)); return r;
}
__device__ __forceinline__ float d_hadd(ull a) {
    unsigned lo, hi; asm("mov.b64 {%0, %1}, %2;" : "=r"(lo), "=r"(hi) : "l"(a));
    return __uint_as_float(lo) + __uint_as_float(hi);
}
__device__ __forceinline__ void d_unpack(ull a, float& lo, float& hi) {
    unsigned x, y; asm("mov.b64 {%0, %1}, %2;" : "=r"(x), "=r"(y) : "l"(a));
    lo = __uint_as_float(x); hi = __uint_as_float(y);
}

// ---------------------------------------------------------------------------
// Repack W (round-4/7 W2 layout): float4 idx = i*4096 + ow*256 + p*32 + lw
// holds { W[i,n,dq+0,p], W[i,n,dq+1,p], W[i,n,dq+2,p], W[i,n,dq+3,p] }
// with n = 8*ow + (lw>>2), dq = (lw&3)*4, ow in [0,16).
// ---------------------------------------------------------------------------
__global__ __launch_bounds__(256) void repack_W(const float* __restrict__ W)
{
    const size_t idx = (size_t)blockIdx.x * 256 + threadIdx.x;
    const int lw = (int)(idx & 31);
    const int p  = (int)((idx >> 5) & 7);
    const int ow = (int)((idx >> 8) & 15);
    const size_t i = idx >> 12;
    const int n  = ow * 8 + (lw >> 2);
    const int dq = (lw & 3) * 4;
    const float* src = W + i * 16384 + n * 128 + p;
    float4 v;
    v.x = src[(dq + 0) * 8]; v.y = src[(dq + 1) * 8];
    v.z = src[(dq + 2) * 8]; v.w = src[(dq + 3) * 8];
    g_W2[idx] = v;
}

// ---------------------------------------------------------------------------
// Pass 0 (uniform coupling): sacc += pred, streamed, zero in-loop sync.
// CTA = (16-n group E, b-half bh: 32 b) x 64 i.
// Lane: slot s=l&7 -> (n = 16E + 2w + (s>>2), dq = (s&3)*4); group g=l>>3.
// W2 fragment: base = i*4096 + (2E + (w>>2))*256 + ((2w&7)<<2);
//   wv[p] = base[p*32 + s]  -> 8 consecutive float4 = 1 wavefront per LDG
//   (4-way duplicated across groups g).
// Lane's 8 b: bl = 4k+g (groups 4B apart -> conflict-free 1-wf LDS).
// x staged pad-33: xs[(ii*8+p)*33 + bl].
// ---------------------------------------------------------------------------
#define SMEM_P0 (512 * 33 * 4)   // 67584 B
__global__ __launch_bounds__(NT, 2)
void caps_pass0(const float* __restrict__ x)
{
    extern __shared__ float xs[];
    const int tid = threadIdx.x;
    const int w   = tid >> 5;
    const int l   = tid & 31;
    const int s   = l & 7;
    const int g   = l >> 3;
    const int E   = blockIdx.x & 7;
    const int bh  = blockIdx.x >> 3;
    const int ic  = blockIdx.y;
    const int i0  = ic * I_B;
    const int b0  = bh * 32;
    const int n   = 16 * E + 2 * w + (s >> 2);
    const int dq  = (s & 3) * 4;
    const int wb  = (2 * E + (w >> 2)) * 256 + ((2 * w & 7) << 2);  // W2 frag base

    // stage x: gmem read coalesced over rem=(ii*8+p); pad-33 kills STS conflicts
    for (int t = tid; t < 32 * I_B * PP; t += NT) {
        const int bl = t >> 9, rem = t & 511;
        xs[rem * 33 + bl] = x[(size_t)(b0 + bl) * (N1 * PP) + (size_t)i0 * PP + rem];
    }
    __syncthreads();

    ull sacc[8][2];
#pragma unroll
    for (int k = 0; k < 8; ++k) { sacc[k][0] = 0ull; sacc[k][1] = 0ull; }

#pragma unroll 1
    for (int ii = 0; ii < I_B; ++ii) {
        const ulonglong2* Wp = (const ulonglong2*)(g_W2
            + (((size_t)(i0 + ii)) << 12) + wb);
        ulonglong2 wv[8];
#pragma unroll
        for (int p = 0; p < 8; ++p) wv[p] = Wp[p * 32 + s];   // 1 wf per LDG

        const float* xr = xs + ii * (8 * 33);
#pragma unroll
        for (int k = 0; k < 8; ++k) {
            const int bl = k * 4 + g;
            ull a = sacc[k][0], b = sacc[k][1];
#pragma unroll
            for (int p = 0; p < 8; ++p) {
                const ull xp = d_dup(xr[p * 33 + bl]);        // 1-wf LDS.32 + dup
                a = d_fma2(xp, wv[p].x, a);
                b = d_fma2(xp, wv[p].y, b);
            }
            sacc[k][0] = a; sacc[k][1] = b;
        }
    }

#pragma unroll
    for (int k = 0; k < 8; ++k) {
        float4 o;
        d_unpack(sacc[k][0], o.x, o.y);
        d_unpack(sacc[k][1], o.z, o.w);
        float* gp = g_partial + ((size_t)ic * BB + (b0 + k * 4 + g)) * NDD
                  + n * DD + dq;
        *(float4*)gp = o;
    }
}

// ---------------------------------------------------------------------------
// Routing pass -- round-7 kernel VERBATIM (known 149us). Block softmax, one
// barrier per ii, 2 CTA/SM. Warp w owns n-groups {8w..8w+8} and {64+8w..};
// lane: n = 8w + (l>>2) (+64g2), dq = (l&3)*4.
// ---------------------------------------------------------------------------
#define BG   4
#define NBB  (BB / BG)          // 16
#define SMEM_RT ((4096 + 8192) * 4 + 2 * 8 * 4 * 8)   // 49.4 KB

__global__ __launch_bounds__(NT, 2)
void caps_route(const float* __restrict__ x, const float* __restrict__ v0in)
{
    extern __shared__ float sm[];
    ull*    x2  = (ull*)sm;                       // 2048 ull = 16 KB (dup'd x)
    float*  v0s = sm + 4096;                      // 8192 f = 32 KB
    float2* red = (float2*)(sm + 4096 + 8192);    // 2*8*4 float2

    const int tid = threadIdx.x;
    const int w   = tid >> 5;
    const int l   = tid & 31;
    const int nb  = w * 8 + (l >> 2);             // n for g2=0 (g2=1: +64)
    const int dq  = (l & 3) * 4;
    const int ib0 = blockIdx.x * I_B;
    const int b0  = blockIdx.y * BG;

    // stage x duplicated as f32x2: x2[bb*512 + ii*8 + p]
    for (int t = tid; t < BG * I_B * PP; t += NT) {
        const int bb = t >> 9, rem = t & 511;
        x2[t] = d_dup(x[(size_t)(b0 + bb) * (N1 * PP) + (size_t)ib0 * PP + rem]);
    }
    for (int t = tid; t < BG * NDD; t += NT) {
        const int bb = t >> 11, rem = t & 2047;
        v0s[t] = v0in[(size_t)(b0 + bb) * NDD + rem];
    }
    __syncthreads();

    ull sacc[2][BG][2];
#pragma unroll
    for (int g2 = 0; g2 < 2; ++g2)
#pragma unroll
        for (int bb = 0; bb < BG; ++bb) { sacc[g2][bb][0] = 0ull; sacc[g2][bb][1] = 0ull; }

#pragma unroll 1
    for (int ii = 0; ii < I_B; ++ii) {
        ull pr[2][BG][2];
        float S[2][BG];
#pragma unroll
        for (int g2 = 0; g2 < 2; ++g2) {
            const ulonglong2* Wp = (const ulonglong2*)(g_W2
                + (((size_t)(ib0 + ii)) << 12) + ((w + 8 * g2) << 8));
            ulonglong2 wv[8];
#pragma unroll
            for (int p = 0; p < 8; ++p) wv[p] = Wp[p * 32 + l];
#pragma unroll
            for (int bb = 0; bb < BG; ++bb) {
                const ulonglong2* xq = (const ulonglong2*)(x2 + bb * 512 + ii * 8);
                const ulonglong2 x01 = xq[0], x23 = xq[1], x45 = xq[2], x67 = xq[3];
                ull a = d_mul2(x01.x, wv[0].x);
                ull b = d_mul2(x01.x, wv[0].y);
                a = d_fma2(x01.y, wv[1].x, a); b = d_fma2(x01.y, wv[1].y, b);
                a = d_fma2(x23.x, wv[2].x, a); b = d_fma2(x23.x, wv[2].y, b);
                a = d_fma2(x23.y, wv[3].x, a); b = d_fma2(x23.y, wv[3].y, b);
                a = d_fma2(x45.x, wv[4].x, a); b = d_fma2(x45.x, wv[4].y, b);
                a = d_fma2(x45.y, wv[5].x, a); b = d_fma2(x45.y, wv[5].y, b);
                a = d_fma2(x67.x, wv[6].x, a); b = d_fma2(x67.x, wv[6].y, b);
                a = d_fma2(x67.y, wv[7].x, a); b = d_fma2(x67.y, wv[7].y, b);
                pr[g2][bb][0] = a; pr[g2][bb][1] = b;

                // agreement + exp + warp sum over this group's 8 n
                const float4 vv = *(const float4*)&v0s[bb * NDD + (nb + 64 * g2) * DD + dq];
                const ull t = d_fma2(a, d_pack(vv.x, vv.y), d_mul2(b, d_pack(vv.z, vv.w)));
                float r = d_hadd(t);
                r += __shfl_xor_sync(0xFFFFFFFFu, r, 1);
                r += __shfl_xor_sync(0xFFFFFFFFu, r, 2);      // full 16-d dot
                const float e = __expf(r);                    // |r| small; no max-sub
                float Sg = e;
                Sg += __shfl_xor_sync(0xFFFFFFFFu, Sg, 4);
                Sg += __shfl_xor_sync(0xFFFFFFFFu, Sg, 8);
                Sg += __shfl_xor_sync(0xFFFFFFFFu, Sg, 16);   // sum of 8 n
                S[g2][bb] = Sg;
                const ull ed = d_dup(e);
                pr[g2][bb][0] = d_mul2(pr[g2][bb][0], ed);    // fold e into pred
                pr[g2][bb][1] = d_mul2(pr[g2][bb][1], ed);
            }
        }
        const int buf = ii & 1;
        if (l == 0) {
#pragma unroll
            for (int bb = 0; bb < BG; ++bb)
                red[(buf * 8 + w) * 4 + bb] = make_float2(S[0][bb], S[1][bb]);
        }
        __syncthreads();                                      // one barrier per ii

        // Z[bb] = sum over 8 warps x 2 groups (broadcast LDS + f32x2 adds)
        ull z[BG] = {0ull, 0ull, 0ull, 0ull};
#pragma unroll
        for (int k = 0; k < 8; ++k) {
            const ulonglong2* rp = (const ulonglong2*)&red[(buf * 8 + k) * 4];
            const ulonglong2 a = rp[0], b = rp[1];
            z[0] = d_add2(z[0], a.x); z[1] = d_add2(z[1], a.y);
            z[2] = d_add2(z[2], b.x); z[3] = d_add2(z[3], b.y);
        }
#pragma unroll
        for (int bb = 0; bb < BG; ++bb) {
            const float Z = d_hadd(z[bb]);                    // sum over all 128 n
            const ull cd  = d_dup(__fdividef(1.0f, Z));
            sacc[0][bb][0] = d_fma2(cd, pr[0][bb][0], sacc[0][bb][0]);
            sacc[0][bb][1] = d_fma2(cd, pr[0][bb][1], sacc[0][bb][1]);
            sacc[1][bb][0] = d_fma2(cd, pr[1][bb][0], sacc[1][bb][0]);
            sacc[1][bb][1] = d_fma2(cd, pr[1][bb][1], sacc[1][bb][1]);
        }
    }

    // write per-(iblock,b) partials
#pragma unroll
    for (int g2 = 0; g2 < 2; ++g2)
#pragma unroll
        for (int bb = 0; bb < BG; ++bb) {
            float4 o;
            d_unpack(sacc[g2][bb][0], o.x, o.y);
            d_unpack(sacc[g2][bb][1], o.z, o.w);
            float* gp = g_partial + ((size_t)blockIdx.x * BB + (b0 + bb)) * NDD
                      + (nb + 64 * g2) * DD + dq;
            *(float4*)gp = o;
        }
}

// ---------------------------------------------------------------------------
// Reduce the NBI partials, scale, squash, write out.
// 4 lanes per (b,n) row; quad shuffles for the norm.
// ---------------------------------------------------------------------------
__global__ __launch_bounds__(256) void reduce_squash_kernel(float* __restrict__ out, float scale)
{
    const int t = blockIdx.x * 256 + threadIdx.x;
    const int r = t >> 2;
    const int quad = t & 3;

    float4 s = make_float4(0.f, 0.f, 0.f, 0.f);
#pragma unroll 3
    for (int blk = 0; blk < NBI; ++blk) {
        const float4 a = *(const float4*)(g_partial
            + ((size_t)blk * (BB * N2) + r) * DD + quad * 4);
        s.x += a.x; s.y += a.y; s.z += a.z; s.w += a.w;
    }
    s.x *= scale; s.y *= scale; s.z *= scale; s.w *= scale;

    float sq = s.x * s.x + s.y * s.y + s.z * s.z + s.w * s.w;
    sq += __shfl_xor_sync(0xFFFFFFFFu, sq, 1);
    sq += __shfl_xor_sync(0xFFFFFFFFu, sq, 2);

    const float norm = sqrtf(sq + 1.1920929e-7f);
    const float f = sq / ((1.0f + sq) * norm);
    *(float4*)(out + (size_t)r * DD + quad * 4) =
        make_float4(f * s.x, f * s.y, f * s.z, f * s.w);
}

// ---------------------------------------------------------------------------
extern "C" void kernel_launch(void* const* d_in, const int* in_sizes, int n_in,
                              void* d_out, int out_size)
{
    const float* x = (const float*)d_in[0];
    const float* W = (const float*)d_in[1];
    if (n_in >= 2 && in_sizes[0] > in_sizes[1]) {   // safety: x is the smaller tensor
        const float* t = x; x = W; W = t;
    }
    float* out = (float*)d_out;

    float* d_v0;
    cudaGetSymbolAddress((void**)&d_v0, g_v0);

    cudaFuncSetAttribute(caps_pass0,
                         cudaFuncAttributeMaxDynamicSharedMemorySize, SMEM_P0);
    cudaFuncSetAttribute(caps_route,
                         cudaFuncAttributeMaxDynamicSharedMemorySize, SMEM_RT);

    // repack W into d-pair warp-coalesced layout (serves both passes)
    repack_W<<<(int)(((size_t)N1 * 4096) / 256), 256>>>(W);

    // iteration 0: uniform coupling -> s0 = (1/128) * sum_i pred
    dim3 grid0(16, NBI);                  // (bh*8 + E, i-block) = 288 CTAs
    caps_pass0<<<grid0, NT, SMEM_P0>>>(x);
    reduce_squash_kernel<<<128, 256>>>(d_v0, 1.0f / 128.0f);

    // iteration 1: softmax(agreement) routing, final squash -> output
    dim3 grid1(NBI, NBB);                 // (i-block, b-block) = 288 CTAs
    caps_route<<<grid1, NT, SMEM_RT>>>(x, d_v0);
    reduce_squash_kernel<<<128, 256>>>(out, 1.0f);
}